// round 8
// baseline (speedup 1.0000x reference)
#include <cuda_runtime.h>
#include <cstdint>

// Shapes (fixed by the problem): B=32, C=4, S=256, L=Din=Dout=256
#define SB 32
#define SC 4
#define SS 256

// Scratch (static device globals — allowed; no runtime allocation)
__device__ float g_corr[SB * SS * SS];        //  8M floats
__device__ float g_adj [SB * SS * SS];        //  8M floats (stored tf32-rounded)
__device__ float g_x   [SB * SC * SS * SS];   // 32M floats (stored tf32-rounded)
__device__ float g_wlc [SS * SS];             // Wl pre-rounded to tf32

// ===========================================================================
// fp32 SGEMM (step 1 only: corr = fm @ fm^T — feeds argmax, stays bit-exact).
// ===========================================================================
template<bool TRANSB, bool BIAS>
__global__ __launch_bounds__(256)
void gemm_kernel(const float* __restrict__ A, const float* __restrict__ B,
                 const float* __restrict__ bias, float* __restrict__ C,
                 int M, int N, int K, int adiv,
                 long strideA, long strideB, long strideC)
{
    const int bz = blockIdx.z;
    A += (long)(bz / adiv) * strideA;
    B += (long)bz * strideB;
    C += (long)bz * strideC;

    __shared__ __align__(16) float As[16][132];
    __shared__ __align__(16) float Bs[16][132];

    const int tid = threadIdx.x;
    const int tx = tid & 15;
    const int ty = tid >> 4;
    const int row0 = blockIdx.y * 128;
    const int col0 = blockIdx.x * 128;

    const int lm  = tid >> 2;
    const int lk4 = (tid & 3) * 4;

    float acc[8][8];
    #pragma unroll
    for (int i = 0; i < 8; i++)
        #pragma unroll
        for (int j = 0; j < 8; j++) acc[i][j] = 0.0f;

    for (int k0 = 0; k0 < K; k0 += 16) {
        {
            float4 v0 = *(const float4*)(A + (long)(row0 + lm     ) * K + k0 + lk4);
            float4 v1 = *(const float4*)(A + (long)(row0 + lm + 64) * K + k0 + lk4);
            As[lk4 + 0][lm] = v0.x; As[lk4 + 1][lm] = v0.y;
            As[lk4 + 2][lm] = v0.z; As[lk4 + 3][lm] = v0.w;
            As[lk4 + 0][lm + 64] = v1.x; As[lk4 + 1][lm + 64] = v1.y;
            As[lk4 + 2][lm + 64] = v1.z; As[lk4 + 3][lm + 64] = v1.w;
        }
        if (TRANSB) {
            float4 v0 = *(const float4*)(B + (long)(col0 + lm     ) * K + k0 + lk4);
            float4 v1 = *(const float4*)(B + (long)(col0 + lm + 64) * K + k0 + lk4);
            Bs[lk4 + 0][lm] = v0.x; Bs[lk4 + 1][lm] = v0.y;
            Bs[lk4 + 2][lm] = v0.z; Bs[lk4 + 3][lm] = v0.w;
            Bs[lk4 + 0][lm + 64] = v1.x; Bs[lk4 + 1][lm + 64] = v1.y;
            Bs[lk4 + 2][lm + 64] = v1.z; Bs[lk4 + 3][lm + 64] = v1.w;
        } else {
            const int bk  = tid >> 5;
            const int bn4 = (tid & 31) * 4;
            float4 v0 = *(const float4*)(B + (long)(k0 + bk    ) * N + col0 + bn4);
            float4 v1 = *(const float4*)(B + (long)(k0 + bk + 8) * N + col0 + bn4);
            *(float4*)(&Bs[bk    ][bn4]) = v0;
            *(float4*)(&Bs[bk + 8][bn4]) = v1;
        }
        __syncthreads();

        #pragma unroll
        for (int kk = 0; kk < 16; kk++) {
            float a[8], b[8];
            *(float4*)&a[0] = *(const float4*)&As[kk][ty * 8];
            *(float4*)&a[4] = *(const float4*)&As[kk][ty * 8 + 4];
            *(float4*)&b[0] = *(const float4*)&Bs[kk][tx * 8];
            *(float4*)&b[4] = *(const float4*)&Bs[kk][tx * 8 + 4];
            #pragma unroll
            for (int i = 0; i < 8; i++)
                #pragma unroll
                for (int j = 0; j < 8; j++)
                    acc[i][j] = fmaf(a[i], b[j], acc[i][j]);
        }
        __syncthreads();
    }

    float bv[8];
    #pragma unroll
    for (int j = 0; j < 8; j++)
        bv[j] = BIAS ? __ldg(&bias[col0 + tx * 8 + j]) : 0.0f;

    #pragma unroll
    for (int i = 0; i < 8; i++) {
        const long r = row0 + ty * 8 + i;
        float4 o0, o1;
        o0.x = acc[i][0] + bv[0]; o0.y = acc[i][1] + bv[1];
        o0.z = acc[i][2] + bv[2]; o0.w = acc[i][3] + bv[3];
        o1.x = acc[i][4] + bv[4]; o1.y = acc[i][5] + bv[5];
        o1.z = acc[i][6] + bv[6]; o1.w = acc[i][7] + bv[7];
        *(float4*)(C + r * N + col0 + tx * 8    ) = o0;
        *(float4*)(C + r * N + col0 + tx * 8 + 4) = o1;
    }
}

// ---- tf32 round-to-nearest convert ----
__device__ __forceinline__ float cvt1_tf32(float v)
{
    uint32_t t;
    asm("cvt.rna.tf32.f32 %0, %1;" : "=r"(t) : "f"(v));
    return __uint_as_float(t);
}
__device__ __forceinline__ float4 cvt_tf32(float4 v)
{
    float4 o;
    o.x = cvt1_tf32(v.x); o.y = cvt1_tf32(v.y);
    o.z = cvt1_tf32(v.z); o.w = cvt1_tf32(v.w);
    return o;
}

// Pre-round a small tensor to tf32 (Wl: 64K elems)
__global__ void round_tf32_kernel(const float* __restrict__ in,
                                  float* __restrict__ out, int n4)
{
    const int i = blockIdx.x * blockDim.x + threadIdx.x;
    if (i < n4)
        *(float4*)(out + i * 4) = cvt_tf32(*(const float4*)(in + i * 4));
}

// ===========================================================================
// TF32 tensor-core GEMM. CVTA/CVTB: convert operand at smem store (skip when
// the producer already tf32-rounded it). ROUND_OUT: store tf32-rounded output.
// ===========================================================================
template<bool BIAS, bool CVTA, bool CVTB, bool ROUND_OUT>
__global__ __launch_bounds__(256, 2)
void gemm_tf32(const float* __restrict__ A, const float* __restrict__ B,
               const float* __restrict__ bias, float* __restrict__ C,
               int M, int N, int K, int adiv,
               long strideA, long strideB, long strideC)
{
    const int bz = blockIdx.z;
    A += (long)(bz / adiv) * strideA;
    B += (long)bz * strideB;
    C += (long)bz * strideC;

    __shared__ __align__(16) float As[2][128][20];   // stride 20: LDSM conflict-free
    __shared__ __align__(16) float Bs[2][16][136];   // stride 136: LDS conflict-free

    const int tid  = threadIdx.x;
    const int lane = tid & 31;
    const int warp = tid >> 5;
    const int wm   = warp >> 2;      // 0..1
    const int wn   = warp & 3;       // 0..3
    const int row0 = blockIdx.y * 128;
    const int col0 = blockIdx.x * 128;

    const int arow = tid >> 2;          // 0..63
    const int acol = (tid & 3) * 4;     // 0,4,8,12
    const int brow = tid >> 5;          // 0..7
    const int bcol = (tid & 31) * 4;    // 0..124

    const int lrow  = lane & 15;
    const int lcol4 = (lane >> 4) << 2;

    float acc[4][4][4];
    #pragma unroll
    for (int mf = 0; mf < 4; mf++)
        #pragma unroll
        for (int nf = 0; nf < 4; nf++)
            #pragma unroll
            for (int r = 0; r < 4; r++) acc[mf][nf][r] = 0.0f;

    // prologue: tile 0
    float4 pa0 = *(const float4*)(A + (long)(row0 + arow     ) * K + acol);
    float4 pa1 = *(const float4*)(A + (long)(row0 + arow + 64) * K + acol);
    float4 pb0 = *(const float4*)(B + (long)(brow    ) * N + col0 + bcol);
    float4 pb1 = *(const float4*)(B + (long)(brow + 8) * N + col0 + bcol);
    *(float4*)(&As[0][arow     ][acol]) = CVTA ? cvt_tf32(pa0) : pa0;
    *(float4*)(&As[0][arow + 64][acol]) = CVTA ? cvt_tf32(pa1) : pa1;
    *(float4*)(&Bs[0][brow    ][bcol]) = CVTB ? cvt_tf32(pb0) : pb0;
    *(float4*)(&Bs[0][brow + 8][bcol]) = CVTB ? cvt_tf32(pb1) : pb1;
    __syncthreads();

    const int nit = K >> 4;
    const int last = nit - 1;
    for (int i = 0; i < nit; i++) {
        const int cur = i & 1;
        if (i < last) {
            const int k0 = (i + 1) << 4;
            pa0 = *(const float4*)(A + (long)(row0 + arow     ) * K + k0 + acol);
            pa1 = *(const float4*)(A + (long)(row0 + arow + 64) * K + k0 + acol);
            pb0 = *(const float4*)(B + (long)(k0 + brow    ) * N + col0 + bcol);
            pb1 = *(const float4*)(B + (long)(k0 + brow + 8) * N + col0 + bcol);
        }

        #pragma unroll
        for (int ks = 0; ks < 2; ks++) {
            const int kc = ks * 8;
            uint32_t a[4][4];
            #pragma unroll
            for (int mf = 0; mf < 4; mf++) {
                const float* p = &As[cur][wm * 64 + mf * 16 + lrow][kc + lcol4];
                uint32_t sa = (uint32_t)__cvta_generic_to_shared(p);
                asm volatile("ldmatrix.sync.aligned.m8n8.x4.shared.b16 {%0,%1,%2,%3}, [%4];"
                             : "=r"(a[mf][0]), "=r"(a[mf][1]), "=r"(a[mf][2]), "=r"(a[mf][3])
                             : "r"(sa));
            }
            uint32_t b[4][2];
            #pragma unroll
            for (int nf = 0; nf < 4; nf++) {
                const int n = wn * 32 + nf * 8 + (lane >> 2);
                b[nf][0] = __float_as_uint(Bs[cur][kc     + (lane & 3)][n]);
                b[nf][1] = __float_as_uint(Bs[cur][kc + 4 + (lane & 3)][n]);
            }
            #pragma unroll
            for (int mf = 0; mf < 4; mf++)
                #pragma unroll
                for (int nf = 0; nf < 4; nf++) {
                    asm volatile(
                        "mma.sync.aligned.m16n8k8.row.col.f32.tf32.tf32.f32 "
                        "{%0,%1,%2,%3}, {%4,%5,%6,%7}, {%8,%9}, {%0,%1,%2,%3};"
                        : "+f"(acc[mf][nf][0]), "+f"(acc[mf][nf][1]),
                          "+f"(acc[mf][nf][2]), "+f"(acc[mf][nf][3])
                        : "r"(a[mf][0]), "r"(a[mf][1]), "r"(a[mf][2]), "r"(a[mf][3]),
                          "r"(b[nf][0]), "r"(b[nf][1]));
                }
        }

        if (i < last) {
            const int nxt = cur ^ 1;
            *(float4*)(&As[nxt][arow     ][acol]) = CVTA ? cvt_tf32(pa0) : pa0;
            *(float4*)(&As[nxt][arow + 64][acol]) = CVTA ? cvt_tf32(pa1) : pa1;
            *(float4*)(&Bs[nxt][brow    ][bcol]) = CVTB ? cvt_tf32(pb0) : pb0;
            *(float4*)(&Bs[nxt][brow + 8][bcol]) = CVTB ? cvt_tf32(pb1) : pb1;
        }
        __syncthreads();
    }

    // epilogue
    #pragma unroll
    for (int mf = 0; mf < 4; mf++) {
        const long r0 = row0 + wm * 64 + mf * 16 + (lane >> 2);
        const long r1 = r0 + 8;
        #pragma unroll
        for (int nf = 0; nf < 4; nf++) {
            const int c = col0 + wn * 32 + nf * 8 + (lane & 3) * 2;
            float b0 = BIAS ? __ldg(&bias[c])     : 0.0f;
            float b1 = BIAS ? __ldg(&bias[c + 1]) : 0.0f;
            float2 o0 = { acc[mf][nf][0] + b0, acc[mf][nf][1] + b1 };
            float2 o1 = { acc[mf][nf][2] + b0, acc[mf][nf][3] + b1 };
            if (ROUND_OUT) {
                o0.x = cvt1_tf32(o0.x); o0.y = cvt1_tf32(o0.y);
                o1.x = cvt1_tf32(o1.x); o1.y = cvt1_tf32(o1.y);
            }
            *(float2*)(C + r0 * N + c) = o0;
            *(float2*)(C + r1 * N + c) = o1;
        }
    }
}

// ---------------------------------------------------------------------------
// JAX threefry2x32 (key = (0, 42)), 20 rounds.
// ---------------------------------------------------------------------------
__device__ __forceinline__ void threefry_0_42(uint32_t x0, uint32_t x1,
                                              uint32_t& o0, uint32_t& o1)
{
    const uint32_t k0 = 0u, k1 = 42u;
    const uint32_t k2 = k0 ^ k1 ^ 0x1BD11BDAu;
    x0 += k0; x1 += k1;
#define TFR(r) { x0 += x1; x1 = (x1 << (r)) | (x1 >> (32 - (r))); x1 ^= x0; }
    TFR(13) TFR(15) TFR(26) TFR(6)
    x0 += k1; x1 += k2 + 1u;
    TFR(17) TFR(29) TFR(16) TFR(24)
    x0 += k2; x1 += k0 + 2u;
    TFR(13) TFR(15) TFR(26) TFR(6)
    x0 += k0; x1 += k1 + 3u;
    TFR(17) TFR(29) TFR(16) TFR(24)
    x0 += k1; x1 += k2 + 4u;
    TFR(13) TFR(15) TFR(26) TFR(6)
    x0 += k2; x1 += k0 + 5u;
#undef TFR
    o0 = x0; o1 = x1;
}

// jax_threefry_partitionable bit generation: counter = 64-bit linear index,
// bits = out0 ^ out1; mantissa-fill uniform in [1e-10, 1); gumbel = -log(-log u)
__device__ __forceinline__ float gumbel_at(uint32_t j)
{
    uint32_t o0, o1;
    threefry_0_42(0u, j, o0, o1);
    const uint32_t bits = o0 ^ o1;
    const float f = __uint_as_float((bits >> 9) | 0x3f800000u) - 1.0f;
    const float u = fmaxf(1e-10f, f + 1e-10f);
    return -logf(-logf(u));
}

__device__ __forceinline__ float gelu_exact(float v)
{
    return 0.5f * v * (1.0f + erff(v * 0.70710678118654752440f));
}

// ---------------------------------------------------------------------------
// Adjacency v3: each thread = 8 consecutive elements; one row = one warp
// (32 x 8 = 256), so the degree is a single warp reduction. Per-element
// arithmetic is the bit-identical sequence of v1/v2. Output stored
// tf32-rounded (identical to what step-3's load-side cvt produced before).
// ---------------------------------------------------------------------------
__global__ __launch_bounds__(256)
void adj_kernel(const float* __restrict__ corr,
                const float* __restrict__ W1, const float* __restrict__ b1,
                const float* __restrict__ W2, const float* __restrict__ b2,
                const float* __restrict__ W3, const float* __restrict__ b3,
                float* __restrict__ adj)
{
    __shared__ float sW1[16], sb1[16], sW2[128], sb2[8], sW3[16], sb3[2];

    const int tid = threadIdx.x;
    if (tid < 16)        sW1[tid]       = W1[tid];
    else if (tid < 32)   sb1[tid - 16]  = b1[tid - 16];
    else if (tid < 160)  sW2[tid - 32]  = W2[tid - 32];
    else if (tid < 168)  sb2[tid - 160] = b2[tid - 160];
    else if (tid < 184)  sW3[tid - 168] = W3[tid - 168];
    else if (tid < 186)  sb3[tid - 184] = b3[tid - 184];
    __syncthreads();

    const int er = tid >> 5;                    // local row 0..7 (= warp id)
    const int r  = blockIdx.x * 8 + er;         // global row (b*256+s)
    const int s  = r & 255;
    const int c0 = (tid & 31) * 8;              // column base
    const long idx = (long)r * 256 + c0;

    float c[8];
    {
        const float4 v0 = *(const float4*)(corr + idx);
        const float4 v1 = *(const float4*)(corr + idx + 4);
        c[0] = v0.x; c[1] = v0.y; c[2] = v0.z; c[3] = v0.w;
        c[4] = v1.x; c[5] = v1.y; c[6] = v1.z; c[7] = v1.w;
    }

    // MLP layer 1+2 for 8 elements, weights read once per (i,j)
    float h2[8][8];
    #pragma unroll
    for (int j = 0; j < 8; j++) {
        const float bj = sb2[j];
        #pragma unroll
        for (int e = 0; e < 8; e++) h2[e][j] = bj;
    }
    #pragma unroll
    for (int i = 0; i < 16; i++) {
        const float w1 = sW1[i], bb = sb1[i];
        float h[8];
        #pragma unroll
        for (int e = 0; e < 8; e++) h[e] = gelu_exact(c[e] * w1 + bb);
        #pragma unroll
        for (int j = 0; j < 8; j++) {
            const float w2 = sW2[i * 8 + j];
            #pragma unroll
            for (int e = 0; e < 8; e++) h2[e][j] += h[e] * w2;
        }
    }
    // layer 3
    float z0[8], z1[8];
    {
        const float bz0 = sb3[0], bz1 = sb3[1];
        #pragma unroll
        for (int e = 0; e < 8; e++) { z0[e] = bz0; z1[e] = bz1; }
    }
    #pragma unroll
    for (int j = 0; j < 8; j++) {
        const float w30 = sW3[j * 2 + 0], w31 = sW3[j * 2 + 1];
        #pragma unroll
        for (int e = 0; e < 8; e++) {
            const float hh = gelu_exact(h2[e][j]);
            z0[e] += hh * w30;
            z1[e] += hh * w31;
        }
    }

    // Gumbel argmax (hard one-hot forward value) + forced diagonal
    int mask = 0;
    #pragma unroll
    for (int e = 0; e < 8; e++) {
        const uint32_t j0 = (uint32_t)(idx + e) * 2u;
        const float g0 = gumbel_at(j0);
        const float g1 = gumbel_at(j0 + 1u);
        int sel = (z0[e] + g0 >= z1[e] + g1) ? 1 : 0;
        if (c0 + e == s) sel = 1;
        mask |= sel << e;
    }

    // integer degree per row — whole row lives in this warp
    const unsigned deg = __reduce_add_sync(0xffffffffu, (unsigned)__popc(mask));
    const float inv = cvt1_tf32(1.0f / (float)deg);  // pre-round for TF32 GEMM

    float4 o0, o1;
    o0.x = (mask &   1) ? inv : 0.0f;
    o0.y = (mask &   2) ? inv : 0.0f;
    o0.z = (mask &   4) ? inv : 0.0f;
    o0.w = (mask &   8) ? inv : 0.0f;
    o1.x = (mask &  16) ? inv : 0.0f;
    o1.y = (mask &  32) ? inv : 0.0f;
    o1.z = (mask &  64) ? inv : 0.0f;
    o1.w = (mask & 128) ? inv : 0.0f;
    *(float4*)(adj + idx)     = o0;
    *(float4*)(adj + idx + 4) = o1;
}

// ---------------------------------------------------------------------------
extern "C" void kernel_launch(void* const* d_in, const int* in_sizes, int n_in,
                              void* d_out, int out_size)
{
    int iF = 0, iFM = 1, iW1 = 2, ib1 = 3, iW2 = 4, ib2 = 5,
        iW3 = 6, ib3 = 7, iWl = 8, ibl = 9;
    if (n_in == 10 && in_sizes[0] == 16 && in_sizes[1] == 128) {
        iW1 = 0; iW2 = 1; iW3 = 2; iWl = 3; ib1 = 4; ib2 = 5; ib3 = 6;
        ibl = 7; iF = 8; iFM = 9;
    }

    const float* features = (const float*)d_in[iF];   // [32,4,256,256]
    const float* fm       = (const float*)d_in[iFM];  // [32,256,256]
    const float* W1       = (const float*)d_in[iW1];
    const float* b1       = (const float*)d_in[ib1];
    const float* W2       = (const float*)d_in[iW2];
    const float* b2       = (const float*)d_in[ib2];
    const float* W3       = (const float*)d_in[iW3];
    const float* b3       = (const float*)d_in[ib3];
    const float* Wl       = (const float*)d_in[iWl];  // [256,256]
    const float* bl       = (const float*)d_in[ibl];  // [256]
    float* out = (float*)d_out;                       // [32,4,256,256]

    float *corr, *adj, *x, *wlc;
    cudaGetSymbolAddress((void**)&corr, g_corr);
    cudaGetSymbolAddress((void**)&adj,  g_adj);
    cudaGetSymbolAddress((void**)&x,    g_x);
    cudaGetSymbolAddress((void**)&wlc,  g_wlc);

    // 0) pre-round Wl to tf32 (once per launch; independent of the chain)
    round_tf32_kernel<<<(SS * SS / 4 + 255) / 256, 256>>>(Wl, wlc, SS * SS / 4);

    // 1) corr[b] = fm[b] @ fm[b]^T   (fp32 — feeds argmax, must stay exact)
    gemm_kernel<true, false><<<dim3(2, 2, SB), 256>>>(
        fm, fm, nullptr, corr, SS, SS, SS, 1,
        (long)SS * SS, (long)SS * SS, (long)SS * SS);

    // 2) adjacency (MLP + threefry gumbel + degree normalize) — bit-exact,
    //    output pre-rounded to tf32
    adj_kernel<<<(SB * SS) / 8, 256>>>(corr, W1, b1, W2, b2, W3, b3, adj);

    // 3) x[b,c] = adj[b] @ features[b,c]   (A pre-rounded; round x at store)
    gemm_tf32<false, false, true, true><<<dim3(2, 2, SB * SC), 256>>>(
        adj, features, nullptr, x, SS, SS, SS, SC,
        (long)SS * SS, (long)SS * SS, (long)SS * SS);

    // 4) out = x_flat @ wlc + bl           (both operands pre-rounded)
    gemm_tf32<true, false, false, false><<<dim3(2, 256, 1), 256>>>(
        x, wlc, bl, out, SB * SC * SS, SS, SS, 1, 0, 0, 0);
}

// round 9
// speedup vs baseline: 1.2128x; 1.2128x over previous
#include <cuda_runtime.h>
#include <cstdint>

// Shapes (fixed by the problem): B=32, C=4, S=256, L=Din=Dout=256
#define SB 32
#define SC 4
#define SS 256

// Scratch (static device globals — allowed; no runtime allocation)
__device__ float g_corr[SB * SS * SS];        //  8M floats
__device__ float g_adj [SB * SS * SS];        //  8M floats (stored tf32-rounded)
__device__ float g_x   [SB * SC * SS * SS];   // 32M floats (stored tf32-rounded)
__device__ float g_wlc [SS * SS];             // Wl pre-rounded to tf32

// ===========================================================================
// fp32 SGEMM (step 1 only: corr = fm @ fm^T — feeds argmax, stays bit-exact).
// ===========================================================================
template<bool TRANSB, bool BIAS>
__global__ __launch_bounds__(256)
void gemm_kernel(const float* __restrict__ A, const float* __restrict__ B,
                 const float* __restrict__ bias, float* __restrict__ C,
                 int M, int N, int K, int adiv,
                 long strideA, long strideB, long strideC)
{
    const int bz = blockIdx.z;
    A += (long)(bz / adiv) * strideA;
    B += (long)bz * strideB;
    C += (long)bz * strideC;

    __shared__ __align__(16) float As[16][132];
    __shared__ __align__(16) float Bs[16][132];

    const int tid = threadIdx.x;
    const int tx = tid & 15;
    const int ty = tid >> 4;
    const int row0 = blockIdx.y * 128;
    const int col0 = blockIdx.x * 128;

    const int lm  = tid >> 2;
    const int lk4 = (tid & 3) * 4;

    float acc[8][8];
    #pragma unroll
    for (int i = 0; i < 8; i++)
        #pragma unroll
        for (int j = 0; j < 8; j++) acc[i][j] = 0.0f;

    for (int k0 = 0; k0 < K; k0 += 16) {
        {
            float4 v0 = *(const float4*)(A + (long)(row0 + lm     ) * K + k0 + lk4);
            float4 v1 = *(const float4*)(A + (long)(row0 + lm + 64) * K + k0 + lk4);
            As[lk4 + 0][lm] = v0.x; As[lk4 + 1][lm] = v0.y;
            As[lk4 + 2][lm] = v0.z; As[lk4 + 3][lm] = v0.w;
            As[lk4 + 0][lm + 64] = v1.x; As[lk4 + 1][lm + 64] = v1.y;
            As[lk4 + 2][lm + 64] = v1.z; As[lk4 + 3][lm + 64] = v1.w;
        }
        if (TRANSB) {
            float4 v0 = *(const float4*)(B + (long)(col0 + lm     ) * K + k0 + lk4);
            float4 v1 = *(const float4*)(B + (long)(col0 + lm + 64) * K + k0 + lk4);
            Bs[lk4 + 0][lm] = v0.x; Bs[lk4 + 1][lm] = v0.y;
            Bs[lk4 + 2][lm] = v0.z; Bs[lk4 + 3][lm] = v0.w;
            Bs[lk4 + 0][lm + 64] = v1.x; Bs[lk4 + 1][lm + 64] = v1.y;
            Bs[lk4 + 2][lm + 64] = v1.z; Bs[lk4 + 3][lm + 64] = v1.w;
        } else {
            const int bk  = tid >> 5;
            const int bn4 = (tid & 31) * 4;
            float4 v0 = *(const float4*)(B + (long)(k0 + bk    ) * N + col0 + bn4);
            float4 v1 = *(const float4*)(B + (long)(k0 + bk + 8) * N + col0 + bn4);
            *(float4*)(&Bs[bk    ][bn4]) = v0;
            *(float4*)(&Bs[bk + 8][bn4]) = v1;
        }
        __syncthreads();

        #pragma unroll
        for (int kk = 0; kk < 16; kk++) {
            float a[8], b[8];
            *(float4*)&a[0] = *(const float4*)&As[kk][ty * 8];
            *(float4*)&a[4] = *(const float4*)&As[kk][ty * 8 + 4];
            *(float4*)&b[0] = *(const float4*)&Bs[kk][tx * 8];
            *(float4*)&b[4] = *(const float4*)&Bs[kk][tx * 8 + 4];
            #pragma unroll
            for (int i = 0; i < 8; i++)
                #pragma unroll
                for (int j = 0; j < 8; j++)
                    acc[i][j] = fmaf(a[i], b[j], acc[i][j]);
        }
        __syncthreads();
    }

    float bv[8];
    #pragma unroll
    for (int j = 0; j < 8; j++)
        bv[j] = BIAS ? __ldg(&bias[col0 + tx * 8 + j]) : 0.0f;

    #pragma unroll
    for (int i = 0; i < 8; i++) {
        const long r = row0 + ty * 8 + i;
        float4 o0, o1;
        o0.x = acc[i][0] + bv[0]; o0.y = acc[i][1] + bv[1];
        o0.z = acc[i][2] + bv[2]; o0.w = acc[i][3] + bv[3];
        o1.x = acc[i][4] + bv[4]; o1.y = acc[i][5] + bv[5];
        o1.z = acc[i][6] + bv[6]; o1.w = acc[i][7] + bv[7];
        *(float4*)(C + r * N + col0 + tx * 8    ) = o0;
        *(float4*)(C + r * N + col0 + tx * 8 + 4) = o1;
    }
}

// ---- tf32 round-to-nearest convert ----
__device__ __forceinline__ float cvt1_tf32(float v)
{
    uint32_t t;
    asm("cvt.rna.tf32.f32 %0, %1;" : "=r"(t) : "f"(v));
    return __uint_as_float(t);
}
__device__ __forceinline__ float4 cvt_tf32(float4 v)
{
    float4 o;
    o.x = cvt1_tf32(v.x); o.y = cvt1_tf32(v.y);
    o.z = cvt1_tf32(v.z); o.w = cvt1_tf32(v.w);
    return o;
}

// Pre-round a small tensor to tf32 (Wl: 64K elems)
__global__ void round_tf32_kernel(const float* __restrict__ in,
                                  float* __restrict__ out, int n4)
{
    const int i = blockIdx.x * blockDim.x + threadIdx.x;
    if (i < n4)
        *(float4*)(out + i * 4) = cvt_tf32(*(const float4*)(in + i * 4));
}

// ===========================================================================
// TF32 tensor-core GEMM. CVTA/CVTB: convert operand at smem store (skip when
// the producer already tf32-rounded it). ROUND_OUT: store tf32-rounded output.
// ===========================================================================
template<bool BIAS, bool CVTA, bool CVTB, bool ROUND_OUT>
__global__ __launch_bounds__(256, 2)
void gemm_tf32(const float* __restrict__ A, const float* __restrict__ B,
               const float* __restrict__ bias, float* __restrict__ C,
               int M, int N, int K, int adiv,
               long strideA, long strideB, long strideC)
{
    const int bz = blockIdx.z;
    A += (long)(bz / adiv) * strideA;
    B += (long)bz * strideB;
    C += (long)bz * strideC;

    __shared__ __align__(16) float As[2][128][20];   // stride 20: LDSM conflict-free
    __shared__ __align__(16) float Bs[2][16][136];   // stride 136: LDS conflict-free

    const int tid  = threadIdx.x;
    const int lane = tid & 31;
    const int warp = tid >> 5;
    const int wm   = warp >> 2;      // 0..1
    const int wn   = warp & 3;       // 0..3
    const int row0 = blockIdx.y * 128;
    const int col0 = blockIdx.x * 128;

    const int arow = tid >> 2;          // 0..63
    const int acol = (tid & 3) * 4;     // 0,4,8,12
    const int brow = tid >> 5;          // 0..7
    const int bcol = (tid & 31) * 4;    // 0..124

    const int lrow  = lane & 15;
    const int lcol4 = (lane >> 4) << 2;

    float acc[4][4][4];
    #pragma unroll
    for (int mf = 0; mf < 4; mf++)
        #pragma unroll
        for (int nf = 0; nf < 4; nf++)
            #pragma unroll
            for (int r = 0; r < 4; r++) acc[mf][nf][r] = 0.0f;

    // prologue: tile 0
    float4 pa0 = *(const float4*)(A + (long)(row0 + arow     ) * K + acol);
    float4 pa1 = *(const float4*)(A + (long)(row0 + arow + 64) * K + acol);
    float4 pb0 = *(const float4*)(B + (long)(brow    ) * N + col0 + bcol);
    float4 pb1 = *(const float4*)(B + (long)(brow + 8) * N + col0 + bcol);
    *(float4*)(&As[0][arow     ][acol]) = CVTA ? cvt_tf32(pa0) : pa0;
    *(float4*)(&As[0][arow + 64][acol]) = CVTA ? cvt_tf32(pa1) : pa1;
    *(float4*)(&Bs[0][brow    ][bcol]) = CVTB ? cvt_tf32(pb0) : pb0;
    *(float4*)(&Bs[0][brow + 8][bcol]) = CVTB ? cvt_tf32(pb1) : pb1;
    __syncthreads();

    const int nit = K >> 4;
    const int last = nit - 1;
    for (int i = 0; i < nit; i++) {
        const int cur = i & 1;
        if (i < last) {
            const int k0 = (i + 1) << 4;
            pa0 = *(const float4*)(A + (long)(row0 + arow     ) * K + k0 + acol);
            pa1 = *(const float4*)(A + (long)(row0 + arow + 64) * K + k0 + acol);
            pb0 = *(const float4*)(B + (long)(k0 + brow    ) * N + col0 + bcol);
            pb1 = *(const float4*)(B + (long)(k0 + brow + 8) * N + col0 + bcol);
        }

        #pragma unroll
        for (int ks = 0; ks < 2; ks++) {
            const int kc = ks * 8;
            uint32_t a[4][4];
            #pragma unroll
            for (int mf = 0; mf < 4; mf++) {
                const float* p = &As[cur][wm * 64 + mf * 16 + lrow][kc + lcol4];
                uint32_t sa = (uint32_t)__cvta_generic_to_shared(p);
                asm volatile("ldmatrix.sync.aligned.m8n8.x4.shared.b16 {%0,%1,%2,%3}, [%4];"
                             : "=r"(a[mf][0]), "=r"(a[mf][1]), "=r"(a[mf][2]), "=r"(a[mf][3])
                             : "r"(sa));
            }
            uint32_t b[4][2];
            #pragma unroll
            for (int nf = 0; nf < 4; nf++) {
                const int n = wn * 32 + nf * 8 + (lane >> 2);
                b[nf][0] = __float_as_uint(Bs[cur][kc     + (lane & 3)][n]);
                b[nf][1] = __float_as_uint(Bs[cur][kc + 4 + (lane & 3)][n]);
            }
            #pragma unroll
            for (int mf = 0; mf < 4; mf++)
                #pragma unroll
                for (int nf = 0; nf < 4; nf++) {
                    asm volatile(
                        "mma.sync.aligned.m16n8k8.row.col.f32.tf32.tf32.f32 "
                        "{%0,%1,%2,%3}, {%4,%5,%6,%7}, {%8,%9}, {%0,%1,%2,%3};"
                        : "+f"(acc[mf][nf][0]), "+f"(acc[mf][nf][1]),
                          "+f"(acc[mf][nf][2]), "+f"(acc[mf][nf][3])
                        : "r"(a[mf][0]), "r"(a[mf][1]), "r"(a[mf][2]), "r"(a[mf][3]),
                          "r"(b[nf][0]), "r"(b[nf][1]));
                }
        }

        if (i < last) {
            const int nxt = cur ^ 1;
            *(float4*)(&As[nxt][arow     ][acol]) = CVTA ? cvt_tf32(pa0) : pa0;
            *(float4*)(&As[nxt][arow + 64][acol]) = CVTA ? cvt_tf32(pa1) : pa1;
            *(float4*)(&Bs[nxt][brow    ][bcol]) = CVTB ? cvt_tf32(pb0) : pb0;
            *(float4*)(&Bs[nxt][brow + 8][bcol]) = CVTB ? cvt_tf32(pb1) : pb1;
        }
        __syncthreads();
    }

    // epilogue
    #pragma unroll
    for (int mf = 0; mf < 4; mf++) {
        const long r0 = row0 + wm * 64 + mf * 16 + (lane >> 2);
        const long r1 = r0 + 8;
        #pragma unroll
        for (int nf = 0; nf < 4; nf++) {
            const int c = col0 + wn * 32 + nf * 8 + (lane & 3) * 2;
            float b0 = BIAS ? __ldg(&bias[c])     : 0.0f;
            float b1 = BIAS ? __ldg(&bias[c + 1]) : 0.0f;
            float2 o0 = { acc[mf][nf][0] + b0, acc[mf][nf][1] + b1 };
            float2 o1 = { acc[mf][nf][2] + b0, acc[mf][nf][3] + b1 };
            if (ROUND_OUT) {
                o0.x = cvt1_tf32(o0.x); o0.y = cvt1_tf32(o0.y);
                o1.x = cvt1_tf32(o1.x); o1.y = cvt1_tf32(o1.y);
            }
            *(float2*)(C + r0 * N + c) = o0;
            *(float2*)(C + r1 * N + c) = o1;
        }
    }
}

// ---------------------------------------------------------------------------
// JAX threefry2x32 (key = (0, 42)), 20 rounds.
// ---------------------------------------------------------------------------
__device__ __forceinline__ void threefry_0_42(uint32_t x0, uint32_t x1,
                                              uint32_t& o0, uint32_t& o1)
{
    const uint32_t k0 = 0u, k1 = 42u;
    const uint32_t k2 = k0 ^ k1 ^ 0x1BD11BDAu;
    x0 += k0; x1 += k1;
#define TFR(r) { x0 += x1; x1 = (x1 << (r)) | (x1 >> (32 - (r))); x1 ^= x0; }
    TFR(13) TFR(15) TFR(26) TFR(6)
    x0 += k1; x1 += k2 + 1u;
    TFR(17) TFR(29) TFR(16) TFR(24)
    x0 += k2; x1 += k0 + 2u;
    TFR(13) TFR(15) TFR(26) TFR(6)
    x0 += k0; x1 += k1 + 3u;
    TFR(17) TFR(29) TFR(16) TFR(24)
    x0 += k1; x1 += k2 + 4u;
    TFR(13) TFR(15) TFR(26) TFR(6)
    x0 += k2; x1 += k0 + 5u;
#undef TFR
    o0 = x0; o1 = x1;
}

// jax_threefry_partitionable bit generation: counter = 64-bit linear index,
// bits = out0 ^ out1; mantissa-fill uniform in [1e-10, 1); gumbel = -log(-log u)
__device__ __forceinline__ float gumbel_at(uint32_t j)
{
    uint32_t o0, o1;
    threefry_0_42(0u, j, o0, o1);
    const uint32_t bits = o0 ^ o1;
    const float f = __uint_as_float((bits >> 9) | 0x3f800000u) - 1.0f;
    const float u = fmaxf(1e-10f, f + 1e-10f);
    return -logf(-logf(u));
}

__device__ __forceinline__ float gelu_exact(float v)
{
    return 0.5f * v * (1.0f + erff(v * 0.70710678118654752440f));
}

// ---------------------------------------------------------------------------
// Adjacency v2 (R7-proven: 4 elems/thread fits registers; v3's 8/thread
// spilled and regressed). Output stored tf32-rounded — identical value to
// what step-3's load-side cvt produced, so numerics are unchanged.
// ---------------------------------------------------------------------------
__global__ __launch_bounds__(256)
void adj_kernel(const float* __restrict__ corr,
                const float* __restrict__ W1, const float* __restrict__ b1,
                const float* __restrict__ W2, const float* __restrict__ b2,
                const float* __restrict__ W3, const float* __restrict__ b3,
                float* __restrict__ adj)
{
    __shared__ float sW1[16], sb1[16], sW2[128], sb2[8], sW3[16], sb3[2];
    __shared__ int wsum[8];

    const int tid = threadIdx.x;
    if (tid < 16)        sW1[tid]       = W1[tid];
    else if (tid < 32)   sb1[tid - 16]  = b1[tid - 16];
    else if (tid < 160)  sW2[tid - 32]  = W2[tid - 32];
    else if (tid < 168)  sb2[tid - 160] = b2[tid - 160];
    else if (tid < 184)  sW3[tid - 168] = W3[tid - 168];
    else if (tid < 186)  sb3[tid - 184] = b3[tid - 184];
    __syncthreads();

    const int er = tid >> 6;                    // local row 0..3
    const int r  = blockIdx.x * 4 + er;         // global row (b*256+s)
    const int s  = r & 255;
    const int c0 = (tid & 63) * 4;              // column base
    const long idx = (long)r * 256 + c0;

    const float4 cv = *(const float4*)(corr + idx);
    float c[4] = {cv.x, cv.y, cv.z, cv.w};

    // MLP layer 1+2 for 4 elements, weights read once per (i,j)
    float h2[4][8];
    #pragma unroll
    for (int j = 0; j < 8; j++) {
        const float bj = sb2[j];
        #pragma unroll
        for (int e = 0; e < 4; e++) h2[e][j] = bj;
    }
    #pragma unroll
    for (int i = 0; i < 16; i++) {
        const float w1 = sW1[i], bb = sb1[i];
        float h[4];
        #pragma unroll
        for (int e = 0; e < 4; e++) h[e] = gelu_exact(c[e] * w1 + bb);
        #pragma unroll
        for (int j = 0; j < 8; j++) {
            const float w2 = sW2[i * 8 + j];
            #pragma unroll
            for (int e = 0; e < 4; e++) h2[e][j] += h[e] * w2;
        }
    }
    // layer 3
    float z0[4], z1[4];
    {
        const float bz0 = sb3[0], bz1 = sb3[1];
        #pragma unroll
        for (int e = 0; e < 4; e++) { z0[e] = bz0; z1[e] = bz1; }
    }
    #pragma unroll
    for (int j = 0; j < 8; j++) {
        const float w30 = sW3[j * 2 + 0], w31 = sW3[j * 2 + 1];
        #pragma unroll
        for (int e = 0; e < 4; e++) {
            const float hh = gelu_exact(h2[e][j]);
            z0[e] += hh * w30;
            z1[e] += hh * w31;
        }
    }

    // Gumbel argmax (hard one-hot forward value) + forced diagonal
    int mask = 0;
    #pragma unroll
    for (int e = 0; e < 4; e++) {
        const uint32_t j0 = (uint32_t)(idx + e) * 2u;
        const float g0 = gumbel_at(j0);
        const float g1 = gumbel_at(j0 + 1u);
        int sel = (z0[e] + g0 >= z1[e] + g1) ? 1 : 0;
        if (c0 + e == s) sel = 1;
        mask |= sel << e;
    }

    // integer degree per row (threads er*64..er*64+63 = warps 2er, 2er+1)
    const unsigned tot = __reduce_add_sync(0xffffffffu, (unsigned)__popc(mask));
    if ((tid & 31) == 0) wsum[tid >> 5] = (int)tot;
    __syncthreads();
    const int deg = wsum[er * 2] + wsum[er * 2 + 1];
    const float inv = cvt1_tf32(1.0f / (float)deg);  // pre-round for TF32 GEMM

    float4 o;
    o.x = (mask & 1) ? inv : 0.0f;
    o.y = (mask & 2) ? inv : 0.0f;
    o.z = (mask & 4) ? inv : 0.0f;
    o.w = (mask & 8) ? inv : 0.0f;
    *(float4*)(adj + idx) = o;
}

// ---------------------------------------------------------------------------
extern "C" void kernel_launch(void* const* d_in, const int* in_sizes, int n_in,
                              void* d_out, int out_size)
{
    int iF = 0, iFM = 1, iW1 = 2, ib1 = 3, iW2 = 4, ib2 = 5,
        iW3 = 6, ib3 = 7, iWl = 8, ibl = 9;
    if (n_in == 10 && in_sizes[0] == 16 && in_sizes[1] == 128) {
        iW1 = 0; iW2 = 1; iW3 = 2; iWl = 3; ib1 = 4; ib2 = 5; ib3 = 6;
        ibl = 7; iF = 8; iFM = 9;
    }

    const float* features = (const float*)d_in[iF];   // [32,4,256,256]
    const float* fm       = (const float*)d_in[iFM];  // [32,256,256]
    const float* W1       = (const float*)d_in[iW1];
    const float* b1       = (const float*)d_in[ib1];
    const float* W2       = (const float*)d_in[iW2];
    const float* b2       = (const float*)d_in[ib2];
    const float* W3       = (const float*)d_in[iW3];
    const float* b3       = (const float*)d_in[ib3];
    const float* Wl       = (const float*)d_in[iWl];  // [256,256]
    const float* bl       = (const float*)d_in[ibl];  // [256]
    float* out = (float*)d_out;                       // [32,4,256,256]

    float *corr, *adj, *x, *wlc;
    cudaGetSymbolAddress((void**)&corr, g_corr);
    cudaGetSymbolAddress((void**)&adj,  g_adj);
    cudaGetSymbolAddress((void**)&x,    g_x);
    cudaGetSymbolAddress((void**)&wlc,  g_wlc);

    // 0) pre-round Wl to tf32 (once per launch; independent of the chain)
    round_tf32_kernel<<<(SS * SS / 4 + 255) / 256, 256>>>(Wl, wlc, SS * SS / 4);

    // 1) corr[b] = fm[b] @ fm[b]^T   (fp32 — feeds argmax, must stay exact)
    gemm_kernel<true, false><<<dim3(2, 2, SB), 256>>>(
        fm, fm, nullptr, corr, SS, SS, SS, 1,
        (long)SS * SS, (long)SS * SS, (long)SS * SS);

    // 2) adjacency (MLP + threefry gumbel + degree normalize) — bit-exact,
    //    output pre-rounded to tf32
    adj_kernel<<<(SB * SS) / 4, 256>>>(corr, W1, b1, W2, b2, W3, b3, adj);

    // 3) x[b,c] = adj[b] @ features[b,c]   (A pre-rounded; round x at store)
    gemm_tf32<false, false, true, true><<<dim3(2, 2, SB * SC), 256>>>(
        adj, features, nullptr, x, SS, SS, SS, SC,
        (long)SS * SS, (long)SS * SS, (long)SS * SS);

    // 4) out = x_flat @ wlc + bl           (both operands pre-rounded)
    gemm_tf32<true, false, false, false><<<dim3(2, 256, 1), 256>>>(
        x, wlc, bl, out, SB * SC * SS, SS, SS, 1, 0, 0, 0);
}

// round 11
// speedup vs baseline: 1.6388x; 1.3513x over previous
#include <cuda_runtime.h>
#include <cstdint>

// Shapes (fixed by the problem): B=32, C=4, S=256, L=Din=Dout=256
#define SB 32
#define SC 4
#define SS 256

// Decision table for the scalar MLP: d(c) = z0(c) - z1(c)
#define TBL_N   65536
#define TBL_MIN (-100.0f)
#define TBL_MAX (100.0f)

// Scratch (static device globals — allowed; no runtime allocation)
__device__ float g_corr[SB * SS * SS];        //  8M floats
__device__ float g_adj [SB * SS * SS];        //  8M floats (stored tf32-rounded)
__device__ float g_x   [SB * SC * SS * SS];   // 32M floats (stored tf32-rounded)
__device__ float g_wlc [SS * SS];             // Wl pre-rounded to tf32
__device__ float g_dtab[TBL_N];               // d(c) lookup table

// ---- tf32 round-to-nearest convert ----
__device__ __forceinline__ float cvt1_tf32(float v)
{
    uint32_t t;
    asm("cvt.rna.tf32.f32 %0, %1;" : "=r"(t) : "f"(v));
    return __uint_as_float(t);
}
__device__ __forceinline__ float4 cvt_tf32(float4 v)
{
    float4 o;
    o.x = cvt1_tf32(v.x); o.y = cvt1_tf32(v.y);
    o.z = cvt1_tf32(v.z); o.w = cvt1_tf32(v.w);
    return o;
}

// Pre-round a small tensor to tf32 (Wl: 64K elems)
__global__ void round_tf32_kernel(const float* __restrict__ in,
                                  float* __restrict__ out, int n4)
{
    const int i = blockIdx.x * blockDim.x + threadIdx.x;
    if (i < n4)
        *(float4*)(out + i * 4) = cvt_tf32(*(const float4*)(in + i * 4));
}

__device__ __forceinline__ float gelu_exact(float v)
{
    return 0.5f * v * (1.0f + erff(v * 0.70710678118654752440f));
}

// ===========================================================================
// Build d(c) table: exact MLP (same arithmetic sequence as the validated
// per-element path) evaluated at 65536 nodes.
// ===========================================================================
__global__ void build_dtab_kernel(const float* __restrict__ W1, const float* __restrict__ b1,
                                  const float* __restrict__ W2, const float* __restrict__ b2,
                                  const float* __restrict__ W3, const float* __restrict__ b3,
                                  float* __restrict__ dtab)
{
    const int k = blockIdx.x * blockDim.x + threadIdx.x;
    if (k >= TBL_N) return;
    const float c = TBL_MIN + (TBL_MAX - TBL_MIN) * ((float)k / (float)(TBL_N - 1));

    float h2[8];
    #pragma unroll
    for (int j = 0; j < 8; j++) h2[j] = __ldg(&b2[j]);
    #pragma unroll
    for (int i = 0; i < 16; i++) {
        const float h = gelu_exact(c * __ldg(&W1[i]) + __ldg(&b1[i]));
        #pragma unroll
        for (int j = 0; j < 8; j++) h2[j] += h * __ldg(&W2[i * 8 + j]);
    }
    float z0 = __ldg(&b3[0]), z1 = __ldg(&b3[1]);
    #pragma unroll
    for (int j = 0; j < 8; j++) {
        const float h = gelu_exact(h2[j]);
        z0 += h * __ldg(&W3[j * 2 + 0]);
        z1 += h * __ldg(&W3[j * 2 + 1]);
    }
    dtab[k] = z0 - z1;
}

// ===========================================================================
// fp32 SGEMM NT, 64x64 tiles (step 1: corr = fm @ fm^T). Accumulation is a
// strict k-ordered fmaf chain — bit-identical to the previous 128x128 kernel.
// 512 CTAs fill the chip (the 128-CTA version left SMs idle).
// ===========================================================================
__global__ __launch_bounds__(256)
void gemm_fp32_nt64(const float* __restrict__ A, const float* __restrict__ B,
                    float* __restrict__ C, long stride)
{
    const int bz = blockIdx.z;
    A += (long)bz * stride;
    B += (long)bz * stride;
    C += (long)bz * stride;

    __shared__ __align__(16) float As[16][68];
    __shared__ __align__(16) float Bs[16][68];

    const int tid = threadIdx.x;
    const int tx = tid & 15;
    const int ty = tid >> 4;
    const int row0 = blockIdx.y * 64;
    const int col0 = blockIdx.x * 64;
    const int lm  = tid >> 2;        // 0..63
    const int lk4 = (tid & 3) * 4;   // 0,4,8,12

    float acc[4][4];
    #pragma unroll
    for (int i = 0; i < 4; i++)
        #pragma unroll
        for (int j = 0; j < 4; j++) acc[i][j] = 0.0f;

    for (int k0 = 0; k0 < SS; k0 += 16) {
        const float4 va = *(const float4*)(A + (long)(row0 + lm) * SS + k0 + lk4);
        const float4 vb = *(const float4*)(B + (long)(col0 + lm) * SS + k0 + lk4);
        As[lk4 + 0][lm] = va.x; As[lk4 + 1][lm] = va.y;
        As[lk4 + 2][lm] = va.z; As[lk4 + 3][lm] = va.w;
        Bs[lk4 + 0][lm] = vb.x; Bs[lk4 + 1][lm] = vb.y;
        Bs[lk4 + 2][lm] = vb.z; Bs[lk4 + 3][lm] = vb.w;
        __syncthreads();

        #pragma unroll
        for (int kk = 0; kk < 16; kk++) {
            float a[4], b[4];
            *(float4*)&a[0] = *(const float4*)&As[kk][ty * 4];
            *(float4*)&b[0] = *(const float4*)&Bs[kk][tx * 4];
            #pragma unroll
            for (int i = 0; i < 4; i++)
                #pragma unroll
                for (int j = 0; j < 4; j++)
                    acc[i][j] = fmaf(a[i], b[j], acc[i][j]);
        }
        __syncthreads();
    }

    #pragma unroll
    for (int i = 0; i < 4; i++) {
        float4 o = { acc[i][0], acc[i][1], acc[i][2], acc[i][3] };
        *(float4*)(C + (long)(row0 + ty * 4 + i) * SS + col0 + tx * 4) = o;
    }
}

// ===========================================================================
// TF32 tensor-core GEMM (steps 3 & 4 — R5-validated core, CVT flags from R9).
// ===========================================================================
template<bool BIAS, bool CVTA, bool CVTB, bool ROUND_OUT>
__global__ __launch_bounds__(256, 2)
void gemm_tf32(const float* __restrict__ A, const float* __restrict__ B,
               const float* __restrict__ bias, float* __restrict__ C,
               int M, int N, int K, int adiv,
               long strideA, long strideB, long strideC)
{
    const int bz = blockIdx.z;
    A += (long)(bz / adiv) * strideA;
    B += (long)bz * strideB;
    C += (long)bz * strideC;

    __shared__ __align__(16) float As[2][128][20];
    __shared__ __align__(16) float Bs[2][16][136];

    const int tid  = threadIdx.x;
    const int lane = tid & 31;
    const int warp = tid >> 5;
    const int wm   = warp >> 2;
    const int wn   = warp & 3;
    const int row0 = blockIdx.y * 128;
    const int col0 = blockIdx.x * 128;

    const int arow = tid >> 2;
    const int acol = (tid & 3) * 4;
    const int brow = tid >> 5;
    const int bcol = (tid & 31) * 4;

    const int lrow  = lane & 15;
    const int lcol4 = (lane >> 4) << 2;

    float acc[4][4][4];
    #pragma unroll
    for (int mf = 0; mf < 4; mf++)
        #pragma unroll
        for (int nf = 0; nf < 4; nf++)
            #pragma unroll
            for (int r = 0; r < 4; r++) acc[mf][nf][r] = 0.0f;

    float4 pa0 = *(const float4*)(A + (long)(row0 + arow     ) * K + acol);
    float4 pa1 = *(const float4*)(A + (long)(row0 + arow + 64) * K + acol);
    float4 pb0 = *(const float4*)(B + (long)(brow    ) * N + col0 + bcol);
    float4 pb1 = *(const float4*)(B + (long)(brow + 8) * N + col0 + bcol);
    *(float4*)(&As[0][arow     ][acol]) = CVTA ? cvt_tf32(pa0) : pa0;
    *(float4*)(&As[0][arow + 64][acol]) = CVTA ? cvt_tf32(pa1) : pa1;
    *(float4*)(&Bs[0][brow    ][bcol]) = CVTB ? cvt_tf32(pb0) : pb0;
    *(float4*)(&Bs[0][brow + 8][bcol]) = CVTB ? cvt_tf32(pb1) : pb1;
    __syncthreads();

    const int nit = K >> 4;
    const int last = nit - 1;
    for (int i = 0; i < nit; i++) {
        const int cur = i & 1;
        if (i < last) {
            const int k0 = (i + 1) << 4;
            pa0 = *(const float4*)(A + (long)(row0 + arow     ) * K + k0 + acol);
            pa1 = *(const float4*)(A + (long)(row0 + arow + 64) * K + k0 + acol);
            pb0 = *(const float4*)(B + (long)(k0 + brow    ) * N + col0 + bcol);
            pb1 = *(const float4*)(B + (long)(k0 + brow + 8) * N + col0 + bcol);
        }

        #pragma unroll
        for (int ks = 0; ks < 2; ks++) {
            const int kc = ks * 8;
            uint32_t a[4][4];
            #pragma unroll
            for (int mf = 0; mf < 4; mf++) {
                const float* p = &As[cur][wm * 64 + mf * 16 + lrow][kc + lcol4];
                uint32_t sa = (uint32_t)__cvta_generic_to_shared(p);
                asm volatile("ldmatrix.sync.aligned.m8n8.x4.shared.b16 {%0,%1,%2,%3}, [%4];"
                             : "=r"(a[mf][0]), "=r"(a[mf][1]), "=r"(a[mf][2]), "=r"(a[mf][3])
                             : "r"(sa));
            }
            uint32_t b[4][2];
            #pragma unroll
            for (int nf = 0; nf < 4; nf++) {
                const int n = wn * 32 + nf * 8 + (lane >> 2);
                b[nf][0] = __float_as_uint(Bs[cur][kc     + (lane & 3)][n]);
                b[nf][1] = __float_as_uint(Bs[cur][kc + 4 + (lane & 3)][n]);
            }
            #pragma unroll
            for (int mf = 0; mf < 4; mf++)
                #pragma unroll
                for (int nf = 0; nf < 4; nf++) {
                    asm volatile(
                        "mma.sync.aligned.m16n8k8.row.col.f32.tf32.tf32.f32 "
                        "{%0,%1,%2,%3}, {%4,%5,%6,%7}, {%8,%9}, {%0,%1,%2,%3};"
                        : "+f"(acc[mf][nf][0]), "+f"(acc[mf][nf][1]),
                          "+f"(acc[mf][nf][2]), "+f"(acc[mf][nf][3])
                        : "r"(a[mf][0]), "r"(a[mf][1]), "r"(a[mf][2]), "r"(a[mf][3]),
                          "r"(b[nf][0]), "r"(b[nf][1]));
                }
        }

        if (i < last) {
            const int nxt = cur ^ 1;
            *(float4*)(&As[nxt][arow     ][acol]) = CVTA ? cvt_tf32(pa0) : pa0;
            *(float4*)(&As[nxt][arow + 64][acol]) = CVTA ? cvt_tf32(pa1) : pa1;
            *(float4*)(&Bs[nxt][brow    ][bcol]) = CVTB ? cvt_tf32(pb0) : pb0;
            *(float4*)(&Bs[nxt][brow + 8][bcol]) = CVTB ? cvt_tf32(pb1) : pb1;
        }
        __syncthreads();
    }

    #pragma unroll
    for (int mf = 0; mf < 4; mf++) {
        const long r0 = row0 + wm * 64 + mf * 16 + (lane >> 2);
        const long r1 = r0 + 8;
        #pragma unroll
        for (int nf = 0; nf < 4; nf++) {
            const int c = col0 + wn * 32 + nf * 8 + (lane & 3) * 2;
            float b0 = BIAS ? __ldg(&bias[c])     : 0.0f;
            float b1 = BIAS ? __ldg(&bias[c + 1]) : 0.0f;
            float2 o0 = { acc[mf][nf][0] + b0, acc[mf][nf][1] + b1 };
            float2 o1 = { acc[mf][nf][2] + b0, acc[mf][nf][3] + b1 };
            if (ROUND_OUT) {
                o0.x = cvt1_tf32(o0.x); o0.y = cvt1_tf32(o0.y);
                o1.x = cvt1_tf32(o1.x); o1.y = cvt1_tf32(o1.y);
            }
            *(float2*)(C + r0 * N + c) = o0;
            *(float2*)(C + r1 * N + c) = o1;
        }
    }
}

// ---------------------------------------------------------------------------
// JAX threefry2x32 (key = (0, 42)), 20 rounds.
// ---------------------------------------------------------------------------
__device__ __forceinline__ void threefry_0_42(uint32_t x0, uint32_t x1,
                                              uint32_t& o0, uint32_t& o1)
{
    const uint32_t k0 = 0u, k1 = 42u;
    const uint32_t k2 = k0 ^ k1 ^ 0x1BD11BDAu;
    x0 += k0; x1 += k1;
#define TFR(r) { x0 += x1; x1 = (x1 << (r)) | (x1 >> (32 - (r))); x1 ^= x0; }
    TFR(13) TFR(15) TFR(26) TFR(6)
    x0 += k1; x1 += k2 + 1u;
    TFR(17) TFR(29) TFR(16) TFR(24)
    x0 += k2; x1 += k0 + 2u;
    TFR(13) TFR(15) TFR(26) TFR(6)
    x0 += k0; x1 += k1 + 3u;
    TFR(17) TFR(29) TFR(16) TFR(24)
    x0 += k1; x1 += k2 + 4u;
    TFR(13) TFR(15) TFR(26) TFR(6)
    x0 += k2; x1 += k0 + 5u;
#undef TFR
    o0 = x0; o1 = x1;
}

// l(j) = -log(u_j), u from jax_threefry_partitionable bits.
// Note g = -log(l); z0+g0>=z1+g1 <=> exp(z0-z1)*l1 >= l0.
__device__ __forceinline__ float neglog_u(uint32_t j)
{
    uint32_t o0, o1;
    threefry_0_42(0u, j, o0, o1);
    const uint32_t bits = o0 ^ o1;
    const float f = __uint_as_float((bits >> 9) | 0x3f800000u) - 1.0f;
    const float u = fmaxf(1e-10f, f + 1e-10f);
    return -logf(u);
}

// ---------------------------------------------------------------------------
// Adjacency v4: MLP replaced by d(c) table lookup + transformed gumbel test.
// 4 elems/thread (register-safe layout from R7).
// ---------------------------------------------------------------------------
__global__ __launch_bounds__(256)
void adj_kernel(const float* __restrict__ corr, const float* __restrict__ dtab,
                float* __restrict__ adj)
{
    __shared__ int wsum[8];

    const int tid = threadIdx.x;
    const int er = tid >> 6;                    // local row 0..3
    const int r  = blockIdx.x * 4 + er;         // global row (b*256+s)
    const int s  = r & 255;
    const int c0 = (tid & 63) * 4;              // column base
    const long idx = (long)r * 256 + c0;

    const float4 cv = *(const float4*)(corr + idx);
    const float c[4] = {cv.x, cv.y, cv.z, cv.w};

    const float scale = (float)(TBL_N - 1) / (TBL_MAX - TBL_MIN);

    int mask = 0;
    #pragma unroll
    for (int e = 0; e < 4; e++) {
        float t = (c[e] - TBL_MIN) * scale;
        t = fminf(fmaxf(t, 0.0f), (float)(TBL_N - 1));
        int i0 = min((int)t, TBL_N - 2);
        const float fr = t - (float)i0;
        const float d0 = __ldg(&dtab[i0]);
        const float d1 = __ldg(&dtab[i0 + 1]);
        const float E = __expf(fmaf(fr, d1 - d0, d0));

        const uint32_t j0 = (uint32_t)(idx + e) * 2u;
        const float l0 = neglog_u(j0);
        const float l1 = neglog_u(j0 + 1u);
        int sel = (E * l1 >= l0) ? 1 : 0;
        if (c0 + e == s) sel = 1;               // forced diagonal
        mask |= sel << e;
    }

    const unsigned tot = __reduce_add_sync(0xffffffffu, (unsigned)__popc(mask));
    if ((tid & 31) == 0) wsum[tid >> 5] = (int)tot;
    __syncthreads();
    const int deg = wsum[er * 2] + wsum[er * 2 + 1];
    const float inv = cvt1_tf32(1.0f / (float)deg);

    float4 o;
    o.x = (mask & 1) ? inv : 0.0f;
    o.y = (mask & 2) ? inv : 0.0f;
    o.z = (mask & 4) ? inv : 0.0f;
    o.w = (mask & 8) ? inv : 0.0f;
    *(float4*)(adj + idx) = o;
}

// ---------------------------------------------------------------------------
extern "C" void kernel_launch(void* const* d_in, const int* in_sizes, int n_in,
                              void* d_out, int out_size)
{
    int iF = 0, iFM = 1, iW1 = 2, ib1 = 3, iW2 = 4, ib2 = 5,
        iW3 = 6, ib3 = 7, iWl = 8, ibl = 9;
    if (n_in == 10 && in_sizes[0] == 16 && in_sizes[1] == 128) {
        iW1 = 0; iW2 = 1; iW3 = 2; iWl = 3; ib1 = 4; ib2 = 5; ib3 = 6;
        ibl = 7; iF = 8; iFM = 9;
    }

    const float* features = (const float*)d_in[iF];   // [32,4,256,256]
    const float* fm       = (const float*)d_in[iFM];  // [32,256,256]
    const float* W1       = (const float*)d_in[iW1];
    const float* b1       = (const float*)d_in[ib1];
    const float* W2       = (const float*)d_in[iW2];
    const float* b2       = (const float*)d_in[ib2];
    const float* W3       = (const float*)d_in[iW3];
    const float* b3       = (const float*)d_in[ib3];
    const float* Wl       = (const float*)d_in[iWl];  // [256,256]
    const float* bl       = (const float*)d_in[ibl];  // [256]
    float* out = (float*)d_out;                       // [32,4,256,256]

    float *corr, *adj, *x, *wlc, *dtab;
    cudaGetSymbolAddress((void**)&corr, g_corr);
    cudaGetSymbolAddress((void**)&adj,  g_adj);
    cudaGetSymbolAddress((void**)&x,    g_x);
    cudaGetSymbolAddress((void**)&wlc,  g_wlc);
    cudaGetSymbolAddress((void**)&dtab, g_dtab);

    // 0a) build decision table (independent of corr)
    build_dtab_kernel<<<TBL_N / 256, 256>>>(W1, b1, W2, b2, W3, b3, dtab);
    // 0b) pre-round Wl to tf32
    round_tf32_kernel<<<(SS * SS / 4 + 255) / 256, 256>>>(Wl, wlc, SS * SS / 4);

    // 1) corr[b] = fm[b] @ fm[b]^T   (fp32, 64x64 tiles — bit-identical chain)
    gemm_fp32_nt64<<<dim3(4, 4, SB), 256>>>(fm, fm, corr, (long)SS * SS);

    // 2) adjacency via table + transformed gumbel test
    adj_kernel<<<(SB * SS) / 4, 256>>>(corr, dtab, adj);

    // 3) x[b,c] = adj[b] @ features[b,c]   (A pre-rounded; round x at store)
    gemm_tf32<false, false, true, true><<<dim3(2, 2, SB * SC), 256>>>(
        adj, features, nullptr, x, SS, SS, SS, SC,
        (long)SS * SS, (long)SS * SS, (long)SS * SS);

    // 4) out = x_flat @ wlc + bl           (both operands pre-rounded)
    gemm_tf32<true, false, false, false><<<dim3(2, 256, 1), 256>>>(
        x, wlc, bl, out, SB * SC * SS, SS, SS, 1, 0, 0, 0);
}

// round 13
// speedup vs baseline: 1.7528x; 1.0695x over previous
#include <cuda_runtime.h>
#include <cstdint>

// Shapes (fixed by the problem): B=32, C=4, S=256, L=Din=Dout=256
#define SB 32
#define SC 4
#define SS 256

// Decision table for the scalar MLP: d(c) = z0(c) - z1(c)
#define TBL_N   65536
#define TBL_MIN (-100.0f)
#define TBL_MAX (100.0f)

// Scratch (static device globals — allowed; no runtime allocation)
__device__ float g_corr[SB * SS * SS];        //  8M floats
__device__ float g_adj [SB * SS * SS];        //  8M floats (stored tf32-rounded)
__device__ float g_y   [SB * SC * SS * SS];   // 32M floats: y = F@Wl (tf32-rounded)
__device__ float g_dtab[TBL_N];               // d(c) lookup table

// ---- tf32 round-to-nearest convert ----
__device__ __forceinline__ float cvt1_tf32(float v)
{
    uint32_t t;
    asm("cvt.rna.tf32.f32 %0, %1;" : "=r"(t) : "f"(v));
    return __uint_as_float(t);
}
__device__ __forceinline__ float4 cvt_tf32(float4 v)
{
    float4 o;
    o.x = cvt1_tf32(v.x); o.y = cvt1_tf32(v.y);
    o.z = cvt1_tf32(v.z); o.w = cvt1_tf32(v.w);
    return o;
}

__device__ __forceinline__ float gelu_exact(float v)
{
    return 0.5f * v * (1.0f + erff(v * 0.70710678118654752440f));
}

// Shared-memory layouts (fat kernel uses the max of the two)
struct TF32Smem { float As[2][128][20]; float Bs[2][16][136]; };  // 37888 B
struct FP32Smem { float As[16][68]; float Bs[16][68]; };          //  8704 B
#define SMEM_BYTES 37888

// ===========================================================================
// fp32 SGEMM NT body, 64x64 tiles (corr = fm @ fm^T; bit-exact k-ordered
// fmaf chain, validated R11).
// ===========================================================================
__device__ void gemm_fp32_nt64_body(char* smem_raw, int bx, int by, int bz,
                                    const float* __restrict__ A,
                                    const float* __restrict__ B,
                                    float* __restrict__ C, long stride)
{
    A += (long)bz * stride;
    B += (long)bz * stride;
    C += (long)bz * stride;

    FP32Smem& S = *(FP32Smem*)smem_raw;

    const int tid = threadIdx.x;
    const int tx = tid & 15;
    const int ty = tid >> 4;
    const int row0 = by * 64;
    const int col0 = bx * 64;
    const int lm  = tid >> 2;
    const int lk4 = (tid & 3) * 4;

    float acc[4][4];
    #pragma unroll
    for (int i = 0; i < 4; i++)
        #pragma unroll
        for (int j = 0; j < 4; j++) acc[i][j] = 0.0f;

    for (int k0 = 0; k0 < SS; k0 += 16) {
        const float4 va = *(const float4*)(A + (long)(row0 + lm) * SS + k0 + lk4);
        const float4 vb = *(const float4*)(B + (long)(col0 + lm) * SS + k0 + lk4);
        S.As[lk4 + 0][lm] = va.x; S.As[lk4 + 1][lm] = va.y;
        S.As[lk4 + 2][lm] = va.z; S.As[lk4 + 3][lm] = va.w;
        S.Bs[lk4 + 0][lm] = vb.x; S.Bs[lk4 + 1][lm] = vb.y;
        S.Bs[lk4 + 2][lm] = vb.z; S.Bs[lk4 + 3][lm] = vb.w;
        __syncthreads();

        #pragma unroll
        for (int kk = 0; kk < 16; kk++) {
            float a[4], b[4];
            *(float4*)&a[0] = *(const float4*)&S.As[kk][ty * 4];
            *(float4*)&b[0] = *(const float4*)&S.Bs[kk][tx * 4];
            #pragma unroll
            for (int i = 0; i < 4; i++)
                #pragma unroll
                for (int j = 0; j < 4; j++)
                    acc[i][j] = fmaf(a[i], b[j], acc[i][j]);
        }
        __syncthreads();
    }

    #pragma unroll
    for (int i = 0; i < 4; i++) {
        float4 o = { acc[i][0], acc[i][1], acc[i][2], acc[i][3] };
        *(float4*)(C + (long)(row0 + ty * 4 + i) * SS + col0 + tx * 4) = o;
    }
}

// ===========================================================================
// TF32 tensor-core GEMM body (R5-validated core; parametrized block coords).
// ===========================================================================
template<bool BIAS, bool CVTA, bool CVTB, bool ROUND_OUT>
__device__ void gemm_tf32_body(char* smem_raw, int bx, int by, int bz,
                               const float* __restrict__ A,
                               const float* __restrict__ B,
                               const float* __restrict__ bias,
                               float* __restrict__ C,
                               int M, int N, int K, int adiv,
                               long strideA, long strideB, long strideC)
{
    A += (long)(bz / adiv) * strideA;
    B += (long)bz * strideB;
    C += (long)bz * strideC;

    TF32Smem& S = *(TF32Smem*)smem_raw;

    const int tid  = threadIdx.x;
    const int lane = tid & 31;
    const int warp = tid >> 5;
    const int wm   = warp >> 2;
    const int wn   = warp & 3;
    const int row0 = by * 128;
    const int col0 = bx * 128;

    const int arow = tid >> 2;
    const int acol = (tid & 3) * 4;
    const int brow = tid >> 5;
    const int bcol = (tid & 31) * 4;

    const int lrow  = lane & 15;
    const int lcol4 = (lane >> 4) << 2;

    float acc[4][4][4];
    #pragma unroll
    for (int mf = 0; mf < 4; mf++)
        #pragma unroll
        for (int nf = 0; nf < 4; nf++)
            #pragma unroll
            for (int r = 0; r < 4; r++) acc[mf][nf][r] = 0.0f;

    float4 pa0 = *(const float4*)(A + (long)(row0 + arow     ) * K + acol);
    float4 pa1 = *(const float4*)(A + (long)(row0 + arow + 64) * K + acol);
    float4 pb0 = *(const float4*)(B + (long)(brow    ) * N + col0 + bcol);
    float4 pb1 = *(const float4*)(B + (long)(brow + 8) * N + col0 + bcol);
    *(float4*)(&S.As[0][arow     ][acol]) = CVTA ? cvt_tf32(pa0) : pa0;
    *(float4*)(&S.As[0][arow + 64][acol]) = CVTA ? cvt_tf32(pa1) : pa1;
    *(float4*)(&S.Bs[0][brow    ][bcol]) = CVTB ? cvt_tf32(pb0) : pb0;
    *(float4*)(&S.Bs[0][brow + 8][bcol]) = CVTB ? cvt_tf32(pb1) : pb1;
    __syncthreads();

    const int nit = K >> 4;
    const int last = nit - 1;
    for (int i = 0; i < nit; i++) {
        const int cur = i & 1;
        if (i < last) {
            const int k0 = (i + 1) << 4;
            pa0 = *(const float4*)(A + (long)(row0 + arow     ) * K + k0 + acol);
            pa1 = *(const float4*)(A + (long)(row0 + arow + 64) * K + k0 + acol);
            pb0 = *(const float4*)(B + (long)(k0 + brow    ) * N + col0 + bcol);
            pb1 = *(const float4*)(B + (long)(k0 + brow + 8) * N + col0 + bcol);
        }

        #pragma unroll
        for (int ks = 0; ks < 2; ks++) {
            const int kc = ks * 8;
            uint32_t a[4][4];
            #pragma unroll
            for (int mf = 0; mf < 4; mf++) {
                const float* p = &S.As[cur][wm * 64 + mf * 16 + lrow][kc + lcol4];
                uint32_t sa = (uint32_t)__cvta_generic_to_shared(p);
                asm volatile("ldmatrix.sync.aligned.m8n8.x4.shared.b16 {%0,%1,%2,%3}, [%4];"
                             : "=r"(a[mf][0]), "=r"(a[mf][1]), "=r"(a[mf][2]), "=r"(a[mf][3])
                             : "r"(sa));
            }
            uint32_t b[4][2];
            #pragma unroll
            for (int nf = 0; nf < 4; nf++) {
                const int n = wn * 32 + nf * 8 + (lane >> 2);
                b[nf][0] = __float_as_uint(S.Bs[cur][kc     + (lane & 3)][n]);
                b[nf][1] = __float_as_uint(S.Bs[cur][kc + 4 + (lane & 3)][n]);
            }
            #pragma unroll
            for (int mf = 0; mf < 4; mf++)
                #pragma unroll
                for (int nf = 0; nf < 4; nf++) {
                    asm volatile(
                        "mma.sync.aligned.m16n8k8.row.col.f32.tf32.tf32.f32 "
                        "{%0,%1,%2,%3}, {%4,%5,%6,%7}, {%8,%9}, {%0,%1,%2,%3};"
                        : "+f"(acc[mf][nf][0]), "+f"(acc[mf][nf][1]),
                          "+f"(acc[mf][nf][2]), "+f"(acc[mf][nf][3])
                        : "r"(a[mf][0]), "r"(a[mf][1]), "r"(a[mf][2]), "r"(a[mf][3]),
                          "r"(b[nf][0]), "r"(b[nf][1]));
                }
        }

        if (i < last) {
            const int nxt = cur ^ 1;
            *(float4*)(&S.As[nxt][arow     ][acol]) = CVTA ? cvt_tf32(pa0) : pa0;
            *(float4*)(&S.As[nxt][arow + 64][acol]) = CVTA ? cvt_tf32(pa1) : pa1;
            *(float4*)(&S.Bs[nxt][brow    ][bcol]) = CVTB ? cvt_tf32(pb0) : pb0;
            *(float4*)(&S.Bs[nxt][brow + 8][bcol]) = CVTB ? cvt_tf32(pb1) : pb1;
        }
        __syncthreads();
    }

    #pragma unroll
    for (int mf = 0; mf < 4; mf++) {
        const long r0 = row0 + wm * 64 + mf * 16 + (lane >> 2);
        const long r1 = r0 + 8;
        #pragma unroll
        for (int nf = 0; nf < 4; nf++) {
            const int c = col0 + wn * 32 + nf * 8 + (lane & 3) * 2;
            float b0 = BIAS ? __ldg(&bias[c])     : 0.0f;
            float b1 = BIAS ? __ldg(&bias[c + 1]) : 0.0f;
            float2 o0 = { acc[mf][nf][0] + b0, acc[mf][nf][1] + b1 };
            float2 o1 = { acc[mf][nf][2] + b0, acc[mf][nf][3] + b1 };
            if (ROUND_OUT) {
                o0.x = cvt1_tf32(o0.x); o0.y = cvt1_tf32(o0.y);
                o1.x = cvt1_tf32(o1.x); o1.y = cvt1_tf32(o1.y);
            }
            *(float2*)(C + r0 * N + c) = o0;
            *(float2*)(C + r1 * N + c) = o1;
        }
    }
}

// d(c) table node: exact MLP (validated R11)
__device__ void dtab_body(int k,
                          const float* __restrict__ W1, const float* __restrict__ b1,
                          const float* __restrict__ W2, const float* __restrict__ b2,
                          const float* __restrict__ W3, const float* __restrict__ b3,
                          float* __restrict__ dtab)
{
    if (k >= TBL_N) return;
    const float c = TBL_MIN + (TBL_MAX - TBL_MIN) * ((float)k / (float)(TBL_N - 1));

    float h2[8];
    #pragma unroll
    for (int j = 0; j < 8; j++) h2[j] = __ldg(&b2[j]);
    #pragma unroll
    for (int i = 0; i < 16; i++) {
        const float h = gelu_exact(c * __ldg(&W1[i]) + __ldg(&b1[i]));
        #pragma unroll
        for (int j = 0; j < 8; j++) h2[j] += h * __ldg(&W2[i * 8 + j]);
    }
    float z0 = __ldg(&b3[0]), z1 = __ldg(&b3[1]);
    #pragma unroll
    for (int j = 0; j < 8; j++) {
        const float h = gelu_exact(h2[j]);
        z0 += h * __ldg(&W3[j * 2 + 0]);
        z1 += h * __ldg(&W3[j * 2 + 1]);
    }
    dtab[k] = z0 - z1;
}

// ===========================================================================
// K1 fat kernel: co-schedule independent work on different pipes.
//   even bids 0..1022  -> y = F@Wl   (tensor pipe, 512 CTAs, 128x128 tiles)
//   odd  bids 1..1023  -> corr = fm@fm^T (fp32 FMA pipe, 512 CTAs, 64x64)
//   bids 1024..1279    -> d(c) table (ALU/MUFU, 256 CTAs)
// ===========================================================================
__global__ __launch_bounds__(256, 2)
void fused_front_kernel(const float* __restrict__ fm,
                        const float* __restrict__ features,
                        const float* __restrict__ Wl,
                        const float* __restrict__ W1, const float* __restrict__ b1,
                        const float* __restrict__ W2, const float* __restrict__ b2,
                        const float* __restrict__ W3, const float* __restrict__ b3,
                        float* __restrict__ corr, float* __restrict__ y,
                        float* __restrict__ dtab)
{
    __shared__ __align__(16) char smem_raw[SMEM_BYTES];
    const int bid = blockIdx.x;

    if (bid < 1024) {
        const int sub = bid >> 1;
        if (bid & 1) {
            // corr: grid (4,4,32) flattened
            gemm_fp32_nt64_body(smem_raw, sub & 3, (sub >> 2) & 3, sub >> 4,
                                fm, fm, corr, (long)SS * SS);
        } else {
            // y = F@Wl: [32768,256]@[256,256], grid (2,256) flattened
            gemm_tf32_body<false, true, true, true>(
                smem_raw, sub & 1, sub >> 1, 0,
                features, Wl, nullptr, y,
                SB * SC * SS, SS, SS, 1, 0, 0, 0);
        }
    } else {
        dtab_body((bid - 1024) * 256 + threadIdx.x, W1, b1, W2, b2, W3, b3, dtab);
    }
}

// K3 standalone wrapper: out = adj @ y + bl (batched)
template<bool BIAS, bool CVTA, bool CVTB, bool ROUND_OUT>
__global__ __launch_bounds__(256, 2)
void gemm_tf32(const float* __restrict__ A, const float* __restrict__ B,
               const float* __restrict__ bias, float* __restrict__ C,
               int M, int N, int K, int adiv,
               long strideA, long strideB, long strideC)
{
    __shared__ __align__(16) char smem_raw[sizeof(TF32Smem)];
    gemm_tf32_body<BIAS, CVTA, CVTB, ROUND_OUT>(
        smem_raw, blockIdx.x, blockIdx.y, blockIdx.z,
        A, B, bias, C, M, N, K, adiv, strideA, strideB, strideC);
}

// ---------------------------------------------------------------------------
// JAX threefry2x32 (key = (0, 42)), 20 rounds.
// ---------------------------------------------------------------------------
__device__ __forceinline__ void threefry_0_42(uint32_t x0, uint32_t x1,
                                              uint32_t& o0, uint32_t& o1)
{
    const uint32_t k0 = 0u, k1 = 42u;
    const uint32_t k2 = k0 ^ k1 ^ 0x1BD11BDAu;
    x0 += k0; x1 += k1;
#define TFR(r) { x0 += x1; x1 = (x1 << (r)) | (x1 >> (32 - (r))); x1 ^= x0; }
    TFR(13) TFR(15) TFR(26) TFR(6)
    x0 += k1; x1 += k2 + 1u;
    TFR(17) TFR(29) TFR(16) TFR(24)
    x0 += k2; x1 += k0 + 2u;
    TFR(13) TFR(15) TFR(26) TFR(6)
    x0 += k0; x1 += k1 + 3u;
    TFR(17) TFR(29) TFR(16) TFR(24)
    x0 += k1; x1 += k2 + 4u;
    TFR(13) TFR(15) TFR(26) TFR(6)
    x0 += k2; x1 += k0 + 5u;
#undef TFR
    o0 = x0; o1 = x1;
}

// l(j) = -log(u_j); decision: z0+g0>=z1+g1 <=> exp(z0-z1)*l1 >= l0.
__device__ __forceinline__ float neglog_u(uint32_t j)
{
    uint32_t o0, o1;
    threefry_0_42(0u, j, o0, o1);
    const uint32_t bits = o0 ^ o1;
    const float f = __uint_as_float((bits >> 9) | 0x3f800000u) - 1.0f;
    const float u = fmaxf(1e-10f, f + 1e-10f);
    return -logf(u);
}

// ---------------------------------------------------------------------------
// Adjacency v4 (R11-validated): table lookup + transformed gumbel test.
// ---------------------------------------------------------------------------
__global__ __launch_bounds__(256)
void adj_kernel(const float* __restrict__ corr, const float* __restrict__ dtab,
                float* __restrict__ adj)
{
    __shared__ int wsum[8];

    const int tid = threadIdx.x;
    const int er = tid >> 6;
    const int r  = blockIdx.x * 4 + er;
    const int s  = r & 255;
    const int c0 = (tid & 63) * 4;
    const long idx = (long)r * 256 + c0;

    const float4 cv = *(const float4*)(corr + idx);
    const float c[4] = {cv.x, cv.y, cv.z, cv.w};

    const float scale = (float)(TBL_N - 1) / (TBL_MAX - TBL_MIN);

    int mask = 0;
    #pragma unroll
    for (int e = 0; e < 4; e++) {
        float t = (c[e] - TBL_MIN) * scale;
        t = fminf(fmaxf(t, 0.0f), (float)(TBL_N - 1));
        int i0 = min((int)t, TBL_N - 2);
        const float fr = t - (float)i0;
        const float d0 = __ldg(&dtab[i0]);
        const float d1 = __ldg(&dtab[i0 + 1]);
        const float E = __expf(fmaf(fr, d1 - d0, d0));

        const uint32_t j0 = (uint32_t)(idx + e) * 2u;
        const float l0 = neglog_u(j0);
        const float l1 = neglog_u(j0 + 1u);
        int sel = (E * l1 >= l0) ? 1 : 0;
        if (c0 + e == s) sel = 1;
        mask |= sel << e;
    }

    const unsigned tot = __reduce_add_sync(0xffffffffu, (unsigned)__popc(mask));
    if ((tid & 31) == 0) wsum[tid >> 5] = (int)tot;
    __syncthreads();
    const int deg = wsum[er * 2] + wsum[er * 2 + 1];
    const float inv = cvt1_tf32(1.0f / (float)deg);

    float4 o;
    o.x = (mask & 1) ? inv : 0.0f;
    o.y = (mask & 2) ? inv : 0.0f;
    o.z = (mask & 4) ? inv : 0.0f;
    o.w = (mask & 8) ? inv : 0.0f;
    *(float4*)(adj + idx) = o;
}

// ---------------------------------------------------------------------------
extern "C" void kernel_launch(void* const* d_in, const int* in_sizes, int n_in,
                              void* d_out, int out_size)
{
    int iF = 0, iFM = 1, iW1 = 2, ib1 = 3, iW2 = 4, ib2 = 5,
        iW3 = 6, ib3 = 7, iWl = 8, ibl = 9;
    if (n_in == 10 && in_sizes[0] == 16 && in_sizes[1] == 128) {
        iW1 = 0; iW2 = 1; iW3 = 2; iWl = 3; ib1 = 4; ib2 = 5; ib3 = 6;
        ibl = 7; iF = 8; iFM = 9;
    }

    const float* features = (const float*)d_in[iF];   // [32,4,256,256]
    const float* fm       = (const float*)d_in[iFM];  // [32,256,256]
    const float* W1       = (const float*)d_in[iW1];
    const float* b1       = (const float*)d_in[ib1];
    const float* W2       = (const float*)d_in[iW2];
    const float* b2       = (const float*)d_in[ib2];
    const float* W3       = (const float*)d_in[iW3];
    const float* b3       = (const float*)d_in[ib3];
    const float* Wl       = (const float*)d_in[iWl];  // [256,256]
    const float* bl       = (const float*)d_in[ibl];  // [256]
    float* out = (float*)d_out;                       // [32,4,256,256]

    float *corr, *adj, *y, *dtab;
    cudaGetSymbolAddress((void**)&corr, g_corr);
    cudaGetSymbolAddress((void**)&adj,  g_adj);
    cudaGetSymbolAddress((void**)&y,    g_y);
    cudaGetSymbolAddress((void**)&dtab, g_dtab);

    // K1: corr = fm@fm^T  ||  y = F@Wl  ||  dtab   (different pipes, one grid)
    fused_front_kernel<<<1280, 256>>>(fm, features, Wl,
                                      W1, b1, W2, b2, W3, b3,
                                      corr, y, dtab);

    // K2: adjacency via table + transformed gumbel test (tf32-rounded store)
    adj_kernel<<<(SB * SS) / 4, 256>>>(corr, dtab, adj);

    // K3: out[b,c] = adj[b] @ y[b,c] + bl   (= (adj@F)@Wl + bl by associativity)
    // R12 bug was strideC=0 (all batches overwrote block 0); fixed to SS*SS.
    gemm_tf32<true, false, false, false><<<dim3(2, 2, SB * SC), 256>>>(
        adj, y, bl, out, SS, SS, SS, SC,
        (long)SS * SS, (long)SS * SS, (long)SS * SS);
}